// round 1
// baseline (speedup 1.0000x reference)
#include <cuda_runtime.h>
#include <math.h>

#define N_BINS 1024
#define N_COPIES 8          // one smem histogram per warp (256 threads / 32)
#define HIST_BLOCKS 1184    // 8 * 148 SMs
#define HIST_THREADS 256

__device__ unsigned int g_counts[N_BINS];

__global__ void zero_counts_kernel() {
    g_counts[threadIdx.x] = 0u;
}

__global__ void __launch_bounds__(HIST_THREADS) hist_kernel(
    const int* __restrict__ idx, long long n)
{
    __shared__ unsigned int sh[N_COPIES][N_BINS];

    // zero the privatized histograms
    unsigned int* flat = &sh[0][0];
    for (int i = threadIdx.x; i < N_COPIES * N_BINS; i += blockDim.x)
        flat[i] = 0u;
    __syncthreads();

    unsigned int* h = sh[threadIdx.x >> 5];  // per-warp copy

    long long tid    = (long long)blockIdx.x * blockDim.x + threadIdx.x;
    long long stride = (long long)gridDim.x * blockDim.x;
    long long n4     = n >> 2;
    const int4* p4   = (const int4*)idx;

    for (long long i = tid; i < n4; i += stride) {
        int4 v = p4[i];
        atomicAdd(&h[v.x & (N_BINS - 1)], 1u);
        atomicAdd(&h[v.y & (N_BINS - 1)], 1u);
        atomicAdd(&h[v.z & (N_BINS - 1)], 1u);
        atomicAdd(&h[v.w & (N_BINS - 1)], 1u);
    }
    // remainder (n not multiple of 4)
    for (long long i = (n4 << 2) + tid; i < n; i += stride)
        atomicAdd(&h[idx[i] & (N_BINS - 1)], 1u);

    __syncthreads();

    // flush: sum the per-warp copies, one global atomic per bin per block
    for (int b = threadIdx.x; b < N_BINS; b += blockDim.x) {
        unsigned int s = 0;
        #pragma unroll
        for (int c = 0; c < N_COPIES; c++) s += sh[c][b];
        atomicAdd(&g_counts[b], s);
    }
}

__global__ void finalize_kernel(float* __restrict__ out, float inv_n) {
    __shared__ float red[32];
    int t = threadIdx.x;                      // 1024 threads, one per bin
    float p = (float)g_counts[t] * inv_n;
    float v = p * logf(p + 1e-8f);

    #pragma unroll
    for (int o = 16; o > 0; o >>= 1) v += __shfl_down_sync(0xFFFFFFFFu, v, o);
    if ((t & 31) == 0) red[t >> 5] = v;
    __syncthreads();
    if (t < 32) {
        float s = red[t];                     // 32 warp partials
        #pragma unroll
        for (int o = 16; o > 0; o >>= 1) s += __shfl_down_sync(0xFFFFFFFFu, s, o);
        if (t == 0) out[0] = expf(-s);
    }
}

extern "C" void kernel_launch(void* const* d_in, const int* in_sizes, int n_in,
                              void* d_out, int out_size) {
    const int* idx = (const int*)d_in[0];
    long long n    = (long long)in_sizes[0];
    float* out     = (float*)d_out;

    zero_counts_kernel<<<1, N_BINS>>>();
    hist_kernel<<<HIST_BLOCKS, HIST_THREADS>>>(idx, n);
    finalize_kernel<<<1, N_BINS>>>(out, 1.0f / (float)n);
}

// round 2
// speedup vs baseline: 1.2162x; 1.2162x over previous
#include <cuda_runtime.h>
#include <math.h>

#define N_BINS 1024
#define N_COPIES 8          // one smem histogram per warp (256 threads / 32)
#define HIST_BLOCKS 592     // 4 * 148 SMs (32KB smem -> up to 7 resident; 4 waves-worth)
#define HIST_THREADS 256

__device__ unsigned int g_counts[N_BINS];   // zero at load; finalize re-zeroes each run

__global__ void __launch_bounds__(HIST_THREADS) hist_kernel(
    const int* __restrict__ idx, long long n)
{
    __shared__ unsigned int sh[N_COPIES][N_BINS];

    unsigned int* flat = &sh[0][0];
    for (int i = threadIdx.x; i < N_COPIES * N_BINS; i += blockDim.x)
        flat[i] = 0u;
    __syncthreads();

    unsigned int* h = sh[threadIdx.x >> 5];  // per-warp copy

    long long tid    = (long long)blockIdx.x * blockDim.x + threadIdx.x;
    long long stride = (long long)gridDim.x * blockDim.x;
    long long n4     = n >> 2;
    const int4* p4   = (const int4*)idx;

    for (long long i = tid; i < n4; i += stride) {
        int4 v = p4[i];
        atomicAdd(&h[v.x & (N_BINS - 1)], 1u);
        atomicAdd(&h[v.y & (N_BINS - 1)], 1u);
        atomicAdd(&h[v.z & (N_BINS - 1)], 1u);
        atomicAdd(&h[v.w & (N_BINS - 1)], 1u);
    }
    for (long long i = (n4 << 2) + tid; i < n; i += stride)
        atomicAdd(&h[idx[i] & (N_BINS - 1)], 1u);

    __syncthreads();

    for (int b = threadIdx.x; b < N_BINS; b += blockDim.x) {
        unsigned int s = 0;
        #pragma unroll
        for (int c = 0; c < N_COPIES; c++) s += sh[c][b];
        atomicAdd(&g_counts[b], s);
    }
}

// Reads counts, computes perplexity, AND resets g_counts to zero for the
// next replay (graph replays the same launches; the invariant is
// "g_counts == 0 at hist entry", maintained here).
__global__ void finalize_kernel(float* __restrict__ out, float inv_n) {
    __shared__ float red[32];
    int t = threadIdx.x;                      // 1024 threads, one per bin
    unsigned int c = g_counts[t];
    g_counts[t] = 0u;                         // reset for next replay
    float p = (float)c * inv_n;
    float v = p * logf(p + 1e-8f);

    #pragma unroll
    for (int o = 16; o > 0; o >>= 1) v += __shfl_down_sync(0xFFFFFFFFu, v, o);
    if ((t & 31) == 0) red[t >> 5] = v;
    __syncthreads();
    if (t < 32) {
        float s = red[t];                     // 32 warp partials
        #pragma unroll
        for (int o = 16; o > 0; o >>= 1) s += __shfl_down_sync(0xFFFFFFFFu, s, o);
        if (t == 0) out[0] = expf(-s);
    }
}

extern "C" void kernel_launch(void* const* d_in, const int* in_sizes, int n_in,
                              void* d_out, int out_size) {
    const int* idx = (const int*)d_in[0];
    long long n    = (long long)in_sizes[0];
    float* out     = (float*)d_out;

    hist_kernel<<<HIST_BLOCKS, HIST_THREADS>>>(idx, n);
    finalize_kernel<<<1, N_BINS>>>(out, 1.0f / (float)n);
}

// round 3
// speedup vs baseline: 1.3636x; 1.1212x over previous
#include <cuda_runtime.h>
#include <math.h>

#define N_BINS 1024
#define N_COPIES 8          // one smem histogram per warp (256 threads / 32)
#define HIST_BLOCKS 592     // 4 * 148 SMs
#define HIST_THREADS 256

__device__ unsigned int g_counts[N_BINS];     // zero at load; reset each run below
__device__ unsigned int g_done;               // arrival counter, reset each run

__global__ void __launch_bounds__(HIST_THREADS) hist_kernel(
    const int* __restrict__ idx, long long n, float inv_n,
    float* __restrict__ out)
{
    __shared__ unsigned int sh[N_COPIES][N_BINS];
    __shared__ bool s_last;
    __shared__ float red[HIST_THREADS / 32];

    unsigned int* flat = &sh[0][0];
    for (int i = threadIdx.x; i < N_COPIES * N_BINS; i += blockDim.x)
        flat[i] = 0u;
    __syncthreads();

    unsigned int* h = sh[threadIdx.x >> 5];  // per-warp copy

    long long tid    = (long long)blockIdx.x * blockDim.x + threadIdx.x;
    long long stride = (long long)gridDim.x * blockDim.x;
    long long n4     = n >> 2;
    const int4* p4   = (const int4*)idx;

    // main loop: 2 outstanding int4 loads per iteration for MLP
    long long i = tid;
    for (; i + stride < n4; i += 2 * stride) {
        int4 a = p4[i];
        int4 b = p4[i + stride];
        atomicAdd(&h[a.x & (N_BINS - 1)], 1u);
        atomicAdd(&h[a.y & (N_BINS - 1)], 1u);
        atomicAdd(&h[a.z & (N_BINS - 1)], 1u);
        atomicAdd(&h[a.w & (N_BINS - 1)], 1u);
        atomicAdd(&h[b.x & (N_BINS - 1)], 1u);
        atomicAdd(&h[b.y & (N_BINS - 1)], 1u);
        atomicAdd(&h[b.z & (N_BINS - 1)], 1u);
        atomicAdd(&h[b.w & (N_BINS - 1)], 1u);
    }
    for (; i < n4; i += stride) {
        int4 a = p4[i];
        atomicAdd(&h[a.x & (N_BINS - 1)], 1u);
        atomicAdd(&h[a.y & (N_BINS - 1)], 1u);
        atomicAdd(&h[a.z & (N_BINS - 1)], 1u);
        atomicAdd(&h[a.w & (N_BINS - 1)], 1u);
    }
    // remainder (n not multiple of 4)
    for (long long r = (n4 << 2) + tid; r < n; r += stride)
        atomicAdd(&h[idx[r] & (N_BINS - 1)], 1u);

    __syncthreads();

    // flush per-warp copies -> global histogram
    for (int b = threadIdx.x; b < N_BINS; b += blockDim.x) {
        unsigned int s = 0;
        #pragma unroll
        for (int c = 0; c < N_COPIES; c++) s += sh[c][b];
        atomicAdd(&g_counts[b], s);
    }

    // last-block-done: fused finalize
    __threadfence();
    if (threadIdx.x == 0)
        s_last = (atomicAdd(&g_done, 1u) == (unsigned)(gridDim.x - 1));
    __syncthreads();

    if (s_last) {
        int t = threadIdx.x;
        volatile unsigned int* gc = g_counts;
        float v = 0.0f;
        #pragma unroll
        for (int k = 0; k < N_BINS / HIST_THREADS; k++) {
            int b = t + k * HIST_THREADS;
            unsigned int c = gc[b];
            g_counts[b] = 0u;                 // reset for next replay
            float p = (float)c * inv_n;
            v += p * logf(p + 1e-8f);
        }
        #pragma unroll
        for (int o = 16; o > 0; o >>= 1) v += __shfl_down_sync(0xFFFFFFFFu, v, o);
        if ((t & 31) == 0) red[t >> 5] = v;
        __syncthreads();
        if (t < 32) {
            float s = (t < HIST_THREADS / 32) ? red[t] : 0.0f;
            #pragma unroll
            for (int o = 4; o > 0; o >>= 1) s += __shfl_down_sync(0xFFFFFFFFu, s, o);
            if (t == 0) {
                out[0] = expf(-s);
                g_done = 0u;                  // reset arrival counter for next replay
            }
        }
    }
}

extern "C" void kernel_launch(void* const* d_in, const int* in_sizes, int n_in,
                              void* d_out, int out_size) {
    const int* idx = (const int*)d_in[0];
    long long n    = (long long)in_sizes[0];
    float* out     = (float*)d_out;

    hist_kernel<<<HIST_BLOCKS, HIST_THREADS>>>(idx, n, 1.0f / (float)n, out);
}